// round 5
// baseline (speedup 1.0000x reference)
#include <cuda_runtime.h>
#include <cuda_bf16.h>

// Problem constants (asserted against in_sizes at launch)
#define N_IN     128
#define N_EXTRA  2
#define N_MID    512
#define N_CAT    (N_IN + N_EXTRA)   // 130

#define RED_BLOCKS 1184             // 148 SMs * 8

// Scratch (allocation-free): per-block partial sums [s[128], sw] and final o[128]
__device__ float g_partial[RED_BLOCKS][N_CAT - 1];   // [1184][129]
__device__ float g_o[N_IN];

// ---------------------------------------------------------------------------
// Kernel 1: weighted reduction  s[c] = sum_b w[b]*x[b,c],  sw = sum_b w[b]
// 256 threads = 8 warps; each warp processes one row/iter, 32 lanes x float4.
// ---------------------------------------------------------------------------
__global__ __launch_bounds__(256, 8)
void reduce_kernel(const float* __restrict__ x,
                   const float* __restrict__ w,
                   int B)
{
    const int rowGroup = threadIdx.x >> 5;   // 0..7 (warp id)
    const int lane     = threadIdx.x & 31;   // column group (float4 index)

    float4 acc = make_float4(0.f, 0.f, 0.f, 0.f);
    float  accw = 0.f;

    const float4* __restrict__ x4 = reinterpret_cast<const float4*>(x);

    int b = blockIdx.x * 8 + rowGroup;
    const int stride = gridDim.x * 8;

    #pragma unroll 4
    for (; b < B; b += stride) {
        const float  wv = __ldg(&w[b]);                    // warp-uniform broadcast
        const float4 xv = __ldg(&x4[(size_t)b * 32 + lane]);
        acc.x = fmaf(wv, xv.x, acc.x);
        acc.y = fmaf(wv, xv.y, acc.y);
        acc.z = fmaf(wv, xv.z, acc.z);
        acc.w = fmaf(wv, xv.w, acc.w);
        if (lane == 0) accw += wv;
    }

    // Cross-warp reduction in shared memory
    __shared__ float s_s[8][N_IN];   // 8 * 128 * 4 = 4 KB
    __shared__ float s_w[8];

    reinterpret_cast<float4*>(s_s[rowGroup])[lane] = acc;
    if (lane == 0) s_w[rowGroup] = accw;
    __syncthreads();

    if (threadIdx.x < N_IN) {
        float v = 0.f;
        #pragma unroll
        for (int g = 0; g < 8; g++) v += s_s[g][threadIdx.x];
        g_partial[blockIdx.x][threadIdx.x] = v;
    } else if (threadIdx.x == N_IN) {
        float v = 0.f;
        #pragma unroll
        for (int g = 0; g < 8; g++) v += s_w[g];
        g_partial[blockIdx.x][N_IN] = v;
    }
}

// ---------------------------------------------------------------------------
// Kernel 2 (single block, 512 threads):
//   reduce partials -> xpbar = [s/sw, p0, p1]
//   hbar = relu(W_in @ xpbar)        (512 x 130)
//   o    = W_out @ hbar              (128 x 512)
// ---------------------------------------------------------------------------
__global__ __launch_bounds__(512, 1)
void gemv_kernel(const float* __restrict__ p,
                 const float* __restrict__ W_in,
                 const float* __restrict__ W_out)
{
    __shared__ float tmp[4][N_IN];   // per-segment column partials
    __shared__ float tmpw[4];
    __shared__ float xpbar[N_CAT];
    __shared__ float hbar[N_MID];

    const int t   = threadIdx.x;      // 0..511
    const int col = t & (N_IN - 1);   // 0..127
    const int seg = t >> 7;           // 0..3

    // --- stage 1: reduce per-block partials, 4 segments in parallel ---
    {
        float v  = 0.f;
        float vw = 0.f;
        #pragma unroll 4
        for (int bs = seg; bs < RED_BLOCKS; bs += 4) {
            v += g_partial[bs][col];
            if (col == 0) vw += g_partial[bs][N_IN];
        }
        tmp[seg][col] = v;
        if (col == 0) tmpw[seg] = vw;
    }
    __syncthreads();

    if (t < N_IN) {
        const float sw = tmpw[0] + tmpw[1] + tmpw[2] + tmpw[3];
        const float s  = tmp[0][t] + tmp[1][t] + tmp[2][t] + tmp[3][t];
        xpbar[t] = s / sw;
    } else if (t == N_IN) {
        xpbar[N_IN]     = __ldg(&p[0]);
        xpbar[N_IN + 1] = __ldg(&p[1]);
    }
    __syncthreads();

    // --- stage 2: hbar = relu(W_in @ xpbar), one output per thread ---
    {
        const float* __restrict__ row = W_in + (size_t)t * N_CAT;
        float a0 = 0.f, a1 = 0.f;
        #pragma unroll 8
        for (int k = 0; k < N_CAT; k += 2) {
            a0 = fmaf(__ldg(&row[k]),     xpbar[k],     a0);
            a1 = fmaf(__ldg(&row[k + 1]), xpbar[k + 1], a1);
        }
        hbar[t] = fmaxf(a0 + a1, 0.f);
    }
    __syncthreads();

    // --- stage 3: o = W_out @ hbar, threads 0..127 ---
    if (t < N_IN) {
        const float* __restrict__ row = W_out + (size_t)t * N_MID;
        float a0 = 0.f, a1 = 0.f, a2 = 0.f, a3 = 0.f;
        #pragma unroll 8
        for (int k = 0; k < N_MID; k += 4) {
            a0 = fmaf(__ldg(&row[k]),     hbar[k],     a0);
            a1 = fmaf(__ldg(&row[k + 1]), hbar[k + 1], a1);
            a2 = fmaf(__ldg(&row[k + 2]), hbar[k + 2], a2);
            a3 = fmaf(__ldg(&row[k + 3]), hbar[k + 3], a3);
        }
        g_o[t] = (a0 + a1) + (a2 + a3);
    }
}

// ---------------------------------------------------------------------------
// Kernel 3: out = x + o  (broadcast add), float4 grid-stride
// ---------------------------------------------------------------------------
__global__ __launch_bounds__(256, 8)
void add_kernel(const float* __restrict__ x,
                float* __restrict__ out,
                long long n4)
{
    __shared__ float4 so[32];   // one row = 128 floats = 32 float4
    if (threadIdx.x < 32)
        so[threadIdx.x] = reinterpret_cast<const float4*>(g_o)[threadIdx.x];
    __syncthreads();

    const float4* __restrict__ x4  = reinterpret_cast<const float4*>(x);
    float4*       __restrict__ o4  = reinterpret_cast<float4*>(out);

    long long idx = (long long)blockIdx.x * blockDim.x + threadIdx.x;
    const long long stride = (long long)gridDim.x * blockDim.x;

    #pragma unroll 4
    for (; idx < n4; idx += stride) {
        float4 xv = __ldg(&x4[idx]);
        const float4 ov = so[idx & 31];
        xv.x += ov.x; xv.y += ov.y; xv.z += ov.z; xv.w += ov.w;
        o4[idx] = xv;
    }
}

// ---------------------------------------------------------------------------
extern "C" void kernel_launch(void* const* d_in, const int* in_sizes, int n_in,
                              void* d_out, int out_size)
{
    const float* x     = (const float*)d_in[0];  // [B, 128]
    const float* w     = (const float*)d_in[1];  // [B, 1]
    const float* p     = (const float*)d_in[2];  // [1, 2]
    const float* W_in  = (const float*)d_in[3];  // [512, 130]
    const float* W_out = (const float*)d_in[4];  // [128, 512]
    float* out = (float*)d_out;

    const int B = in_sizes[0] / N_IN;

    reduce_kernel<<<RED_BLOCKS, 256>>>(x, w, B);
    gemv_kernel<<<1, 512>>>(p, W_in, W_out);

    const long long n4 = (long long)B * (N_IN / 4);
    add_kernel<<<2368, 256>>>(x, out, n4);
}

// round 6
// speedup vs baseline: 1.5837x; 1.5837x over previous
#include <cuda_runtime.h>
#include <cuda_bf16.h>

// Problem constants
#define N_IN   128
#define N_MID  512
#define N_CAT  130

#define RB 148          // reduce blocks (1 per SM)
#define RT 512          // reduce threads (16 warps)
#define PQ 33           // float4 quads per partial row (132 floats: 128 sums, sw, 3 pad)

// Scratch (allocation-free)
__device__ float4 g_partial4[RB * PQ];
__device__ float  g_o[N_IN];

// ---------------------------------------------------------------------------
// Kernel 1: weighted reduction  s[c] = sum_b w[b]*x[b,c],  sw = sum_b w[b]
// 148 blocks x 512 threads. Warp-per-row, 32 lanes x float4 = 512B/row.
// Forward stream leaves the tail of x hot in L2 for the add kernel.
// ---------------------------------------------------------------------------
__global__ __launch_bounds__(RT, 1)
void reduce_kernel(const float* __restrict__ x,
                   const float* __restrict__ w,
                   int B)
{
    const int wid  = threadIdx.x >> 5;   // 0..15
    const int lane = threadIdx.x & 31;

    const float4* __restrict__ x4 = reinterpret_cast<const float4*>(x);

    float4 acc = make_float4(0.f, 0.f, 0.f, 0.f);
    float  accw = 0.f;

    const int stride = RB * 16;          // 2368 rows per grid step

    #pragma unroll 8
    for (int b = blockIdx.x * 16 + wid; b < B; b += stride) {
        const float  wv = __ldg(&w[b]);                       // warp-uniform
        const float4 xv = __ldg(&x4[(size_t)b * 32 + lane]);
        acc.x = fmaf(wv, xv.x, acc.x);
        acc.y = fmaf(wv, xv.y, acc.y);
        acc.z = fmaf(wv, xv.z, acc.z);
        acc.w = fmaf(wv, xv.w, acc.w);
        if (lane == 0) accw += wv;
    }

    __shared__ float s_s[16][N_IN];      // 8 KB
    __shared__ float s_w[16];
    __shared__ __align__(16) float fin[4 * PQ];   // 132 floats

    reinterpret_cast<float4*>(s_s[wid])[lane] = acc;
    if (lane == 0) s_w[wid] = accw;
    __syncthreads();

    if (threadIdx.x < N_IN) {
        float v = 0.f;
        #pragma unroll
        for (int g = 0; g < 16; g++) v += s_s[g][threadIdx.x];
        fin[threadIdx.x] = v;
    } else if (threadIdx.x == N_IN) {
        float v = 0.f;
        #pragma unroll
        for (int g = 0; g < 16; g++) v += s_w[g];
        fin[N_IN] = v;
    } else if (threadIdx.x < 4 * PQ) {
        fin[threadIdx.x] = 0.f;          // pad cols 129..131
    }
    __syncthreads();

    if (threadIdx.x < PQ)
        g_partial4[blockIdx.x * PQ + threadIdx.x] =
            reinterpret_cast<const float4*>(fin)[threadIdx.x];
}

// ---------------------------------------------------------------------------
// Kernel 2 (single block, 512 threads): funnel + two GEMVs, all coalesced.
//   stage 1: reduce 148 partial rows -> xpbar = [s/sw, p0, p1]
//   stage 2: hbar = relu(W_in @ xpbar)  — warp-per-row, float2 row reads
//   stage 3: o    = W_out @ hbar        — warp-per-row, float4 row reads
// ---------------------------------------------------------------------------
__global__ __launch_bounds__(512, 1)
void gemv_kernel(const float* __restrict__ p,
                 const float* __restrict__ W_in,
                 const float* __restrict__ W_out)
{
    __shared__ float4 s1[15 * PQ];                     // 7.9 KB
    __shared__ __align__(16) float colsum[4 * PQ];     // 132
    __shared__ __align__(16) float xp[132];            // 130 used (pad to even f2)
    __shared__ __align__(16) float hb[N_MID];          // 512

    const int t    = threadIdx.x;
    const int wid  = t >> 5;
    const int lane = t & 31;

    // --- stage 1: column funnel over 148 partial rows (coalesced float4) ---
    if (t < 15 * PQ) {                                  // 495 threads
        const int q = t % PQ, g = t / PQ;
        float4 a = make_float4(0.f, 0.f, 0.f, 0.f);
        for (int r = g; r < RB; r += 15) {              // 10 iters max
            const float4 v = g_partial4[r * PQ + q];
            a.x += v.x; a.y += v.y; a.z += v.z; a.w += v.w;
        }
        s1[g * PQ + q] = a;
    }
    __syncthreads();

    if (t < PQ) {
        float4 a = make_float4(0.f, 0.f, 0.f, 0.f);
        #pragma unroll
        for (int g = 0; g < 15; g++) {
            const float4 v = s1[g * PQ + t];
            a.x += v.x; a.y += v.y; a.z += v.z; a.w += v.w;
        }
        reinterpret_cast<float4*>(colsum)[t] = a;
    }
    __syncthreads();

    if (t < N_IN) {
        xp[t] = colsum[t] / colsum[N_IN];
    } else if (t == N_IN) {
        xp[N_IN]     = __ldg(&p[0]);
        xp[N_IN + 1] = __ldg(&p[1]);
        xp[130] = 0.f; xp[131] = 0.f;
    }
    __syncthreads();

    // --- stage 2: hbar = relu(W_in @ xpbar) — warp per row, float2 loads ---
    {
        const float2* __restrict__ xp2 = reinterpret_cast<const float2*>(xp);
        for (int r = wid; r < N_MID; r += 16) {          // 32 rows/warp
            const float2* __restrict__ row =
                reinterpret_cast<const float2*>(W_in + (size_t)r * N_CAT);
            float2 w0 = __ldg(&row[lane]);
            float2 w1 = __ldg(&row[lane + 32]);
            float2 x0 = xp2[lane];
            float2 x1 = xp2[lane + 32];
            float a = fmaf(w0.x, x0.x, w0.y * x0.y);
            a = fmaf(w1.x, x1.x, fmaf(w1.y, x1.y, a));
            if (lane == 0) {                             // remainder f2 idx 64 (cols 128,129)
                const float2 w2 = __ldg(&row[64]);
                const float2 x2 = xp2[64];
                a = fmaf(w2.x, x2.x, fmaf(w2.y, x2.y, a));
            }
            #pragma unroll
            for (int s = 16; s; s >>= 1) a += __shfl_xor_sync(0xFFFFFFFFu, a, s);
            if (lane == 0) hb[r] = fmaxf(a, 0.f);
        }
    }
    __syncthreads();

    // --- stage 3: o = W_out @ hbar — warp per row, float4 loads ---
    {
        const float4* __restrict__ hb4 = reinterpret_cast<const float4*>(hb);
        for (int r = wid; r < N_IN; r += 16) {           // 8 rows/warp
            const float4* __restrict__ row =
                reinterpret_cast<const float4*>(W_out + (size_t)r * N_MID);
            float a = 0.f;
            #pragma unroll
            for (int j = 0; j < 4; j++) {
                const float4 wv = __ldg(&row[lane + 32 * j]);
                const float4 hv = hb4[lane + 32 * j];
                a = fmaf(wv.x, hv.x, a);
                a = fmaf(wv.y, hv.y, a);
                a = fmaf(wv.z, hv.z, a);
                a = fmaf(wv.w, hv.w, a);
            }
            #pragma unroll
            for (int s = 16; s; s >>= 1) a += __shfl_xor_sync(0xFFFFFFFFu, a, s);
            if (lane == 0) g_o[r] = a;
        }
    }
}

// ---------------------------------------------------------------------------
// Kernel 3: out = x + o  (broadcast add)
// REVERSED traversal: reduce streamed x forward, so the tail of x is hot in
// L2 (x=128MB vs L2=126MB). Reading backward hits L2; streaming (.cs) stores
// keep the out write stream from evicting x. Steady state: reads ~L2-fed,
// kernel is DRAM-write-bound (~128MB).
// ---------------------------------------------------------------------------
__global__ __launch_bounds__(256, 8)
void add_kernel(const float* __restrict__ x,
                float* __restrict__ out,
                long long n4)
{
    __shared__ float4 so[32];            // one row = 32 float4
    if (threadIdx.x < 32)
        so[threadIdx.x] = reinterpret_cast<const float4*>(g_o)[threadIdx.x];
    __syncthreads();

    const float4* __restrict__ x4 = reinterpret_cast<const float4*>(x);
    float4*       __restrict__ o4 = reinterpret_cast<float4*>(out);

    const long long stride = (long long)gridDim.x * blockDim.x;

    #pragma unroll 4
    for (long long idx = (long long)blockIdx.x * blockDim.x + threadIdx.x;
         idx < n4; idx += stride) {
        const long long j = n4 - 1 - idx;            // walk backward through x
        float4 xv = __ldg(&x4[j]);
        const float4 ov = so[(int)(j & 31)];
        xv.x += ov.x; xv.y += ov.y; xv.z += ov.z; xv.w += ov.w;
        __stcs(&o4[j], xv);                          // evict-first store
    }
}

// ---------------------------------------------------------------------------
extern "C" void kernel_launch(void* const* d_in, const int* in_sizes, int n_in,
                              void* d_out, int out_size)
{
    const float* x     = (const float*)d_in[0];  // [B, 128]
    const float* w     = (const float*)d_in[1];  // [B, 1]
    const float* p     = (const float*)d_in[2];  // [1, 2]
    const float* W_in  = (const float*)d_in[3];  // [512, 130]
    const float* W_out = (const float*)d_in[4];  // [128, 512]
    float* out = (float*)d_out;

    const int B = in_sizes[0] / N_IN;

    reduce_kernel<<<RB, RT>>>(x, w, B);
    gemv_kernel<<<1, 512>>>(p, W_in, W_out);

    const long long n4 = (long long)B * (N_IN / 4);
    add_kernel<<<1184, 256>>>(x, out, n4);
}

// round 9
// speedup vs baseline: 1.8868x; 1.1914x over previous
#include <cuda_runtime.h>
#include <cuda_bf16.h>

// Problem constants
#define N_IN   128
#define N_MID  512
#define N_CAT  130

#define RB     148               // blocks = SMs (co-residency for grid barrier)
#define RT     1024              // threads per block (32 warps)
#define WARPS  32
#define SLOTS  (RB * WARPS)      // 4736 warp-slots
#define PQ     33                // float4 quads per partial row (132 floats)

// Scratch (allocation-free)
__device__ float4       g_partial4[RB * PQ];
__device__ unsigned int g_bar;

// Tiny init: reset barrier counter each launch (keeps replays deterministic)
__global__ void init_kernel() { g_bar = 0u; }

// ---------------------------------------------------------------------------
// ONE persistent kernel:
//   phase 1: weighted reduction of x (forward, grid-strided per warp-slot)
//   grid barrier (all 148 blocks resident)
//   gemv (redundant per block, weights from L2): xpbar -> hbar -> o[128]
//   phase 2: out = x + o, each warp re-reads ITS OWN rows newest-first
//            (reverse k) so reads hit L2; __stcs writes stay evict-first.
// ---------------------------------------------------------------------------
__global__ __launch_bounds__(RT, 1)
void fused_kernel(const float* __restrict__ x,
                  const float* __restrict__ w,
                  const float* __restrict__ p,
                  const float* __restrict__ W_in,
                  const float* __restrict__ W_out,
                  float* __restrict__ out,
                  int B)
{
    const int t    = threadIdx.x;
    const int wid  = t >> 5;          // 0..31
    const int lane = t & 31;
    const int slot = blockIdx.x * WARPS + wid;

    const float4* __restrict__ x4 = reinterpret_cast<const float4*>(x);
    float4*       __restrict__ o4 = reinterpret_cast<float4*>(out);

    __shared__ float s_s[WARPS][N_IN];           // 16 KB
    __shared__ float s_w[WARPS];
    __shared__ __align__(16) float fin[4 * PQ];  // 132

    // ---------------- phase 1: weighted reduction ----------------
    {
        float4 acc = make_float4(0.f, 0.f, 0.f, 0.f);
        float  accw = 0.f;

        #pragma unroll 4
        for (int b = slot; b < B; b += SLOTS) {
            const float  wv = __ldg(&w[b]);                      // warp-uniform
            const float4 xv = __ldg(&x4[(size_t)b * 32 + lane]);
            acc.x = fmaf(wv, xv.x, acc.x);
            acc.y = fmaf(wv, xv.y, acc.y);
            acc.z = fmaf(wv, xv.z, acc.z);
            acc.w = fmaf(wv, xv.w, acc.w);
            if (lane == 0) accw += wv;
        }

        reinterpret_cast<float4*>(s_s[wid])[lane] = acc;
        if (lane == 0) s_w[wid] = accw;
        __syncthreads();

        if (t < N_IN) {
            float v = 0.f;
            #pragma unroll
            for (int g = 0; g < WARPS; g++) v += s_s[g][t];
            fin[t] = v;
        } else if (t == N_IN) {
            float v = 0.f;
            #pragma unroll
            for (int g = 0; g < WARPS; g++) v += s_w[g];
            fin[N_IN] = v;
        } else if (t < 4 * PQ) {
            fin[t] = 0.f;                                        // pad 129..131
        }
        __syncthreads();

        if (t < PQ)
            g_partial4[blockIdx.x * PQ + t] =
                reinterpret_cast<const float4*>(fin)[t];
    }

    // ---------------- grid barrier ----------------
    __threadfence();          // publish g_partial4 (gpu scope)
    __syncthreads();
    if (t == 0) {
        atomicAdd(&g_bar, 1u);
        while (*((volatile unsigned int*)&g_bar) < (unsigned int)RB) { }
        __threadfence();      // acquire: order subsequent partial reads
    }
    __syncthreads();

    // ---------------- gemv (redundant per block, all from L2) ----------------
    __shared__ float tmp[7][4 * PQ];             // 7 x 132
    __shared__ __align__(16) float xp[132];
    __shared__ __align__(16) float hb[N_MID];
    __shared__ __align__(16) float so[N_IN];

    // funnel 148 partial rows -> colsum
    if (t < 7 * 132) {                            // 924 threads
        const int col = t % 132, g = t / 132;
        const float* __restrict__ gp = reinterpret_cast<const float*>(g_partial4);
        float v = 0.f;
        #pragma unroll 4
        for (int r = g; r < RB; r += 7) v += gp[r * 132 + col];
        tmp[g][col] = v;
    }
    __syncthreads();
    if (t < 132) {
        float v = 0.f;
        #pragma unroll
        for (int g = 0; g < 7; g++) v += tmp[g][t];
        tmp[0][t] = v;                            // colsum
    }
    __syncthreads();
    if (t < N_IN) {
        xp[t] = tmp[0][t] / tmp[0][N_IN];
    } else if (t == N_IN) {
        xp[N_IN]     = __ldg(&p[0]);
        xp[N_IN + 1] = __ldg(&p[1]);
        xp[130] = 0.f; xp[131] = 0.f;
    }
    __syncthreads();

    // hbar = relu(W_in @ xpbar): warp-per-row, 16 rows/warp, float2 rows
    {
        const float2* __restrict__ xp2 = reinterpret_cast<const float2*>(xp);
        const float2 x0 = xp2[lane];
        const float2 x1 = xp2[lane + 32];
        #pragma unroll 2
        for (int r = wid; r < N_MID; r += WARPS) {
            const float2* __restrict__ row =
                reinterpret_cast<const float2*>(W_in + (size_t)r * N_CAT);
            const float2 w0 = __ldg(&row[lane]);
            const float2 w1 = __ldg(&row[lane + 32]);
            float a = fmaf(w0.x, x0.x, w0.y * x0.y);
            a = fmaf(w1.x, x1.x, fmaf(w1.y, x1.y, a));
            if (lane == 0) {                      // cols 128,129
                const float2 w2 = __ldg(&row[64]);
                a = fmaf(w2.x, xp[128], fmaf(w2.y, xp[129], a));
            }
            #pragma unroll
            for (int s = 16; s; s >>= 1) a += __shfl_xor_sync(0xFFFFFFFFu, a, s);
            if (lane == 0) hb[r] = fmaxf(a, 0.f);
        }
    }
    __syncthreads();

    // o = W_out @ hbar: warp-per-row, 4 rows/warp, float4 rows
    {
        const float4* __restrict__ hb4 = reinterpret_cast<const float4*>(hb);
        const float4 h0 = hb4[lane];
        const float4 h1 = hb4[lane + 32];
        const float4 h2 = hb4[lane + 64];
        const float4 h3 = hb4[lane + 96];
        #pragma unroll
        for (int r = wid; r < N_IN; r += WARPS) {
            const float4* __restrict__ row =
                reinterpret_cast<const float4*>(W_out + (size_t)r * N_MID);
            const float4 w0 = __ldg(&row[lane]);
            const float4 w1 = __ldg(&row[lane + 32]);
            const float4 w2 = __ldg(&row[lane + 64]);
            const float4 w3 = __ldg(&row[lane + 96]);
            float a = fmaf(w0.x, h0.x, w0.y * h0.y);
            a = fmaf(w0.z, h0.z, fmaf(w0.w, h0.w, a));
            a = fmaf(w1.x, h1.x, fmaf(w1.y, h1.y, a));
            a = fmaf(w1.z, h1.z, fmaf(w1.w, h1.w, a));
            a = fmaf(w2.x, h2.x, fmaf(w2.y, h2.y, a));
            a = fmaf(w2.z, h2.z, fmaf(w2.w, h2.w, a));
            a = fmaf(w3.x, h3.x, fmaf(w3.y, h3.y, a));
            a = fmaf(w3.z, h3.z, fmaf(w3.w, h3.w, a));
            #pragma unroll
            for (int s = 16; s; s >>= 1) a += __shfl_xor_sync(0xFFFFFFFFu, a, s);
            if (lane == 0) so[r] = a;
        }
    }
    __syncthreads();

    // ---------------- phase 2: out = x + o (reverse over own rows) ----------
    {
        const float4 ov = reinterpret_cast<const float4*>(so)[lane];
        if (slot < B) {
            const int kmax = (B - 1 - slot) / SLOTS + 1;  // rows for this slot
            #pragma unroll 4
            for (int k = kmax - 1; k >= 0; --k) {
                const size_t b = (size_t)slot + (size_t)k * SLOTS;
                float4 xv = __ldg(&x4[b * 32 + lane]);
                xv.x += ov.x; xv.y += ov.y; xv.z += ov.z; xv.w += ov.w;
                __stcs(&o4[b * 32 + lane], xv);           // evict-first store
            }
        }
    }
}

// ---------------------------------------------------------------------------
extern "C" void kernel_launch(void* const* d_in, const int* in_sizes, int n_in,
                              void* d_out, int out_size)
{
    const float* x     = (const float*)d_in[0];  // [B, 128]
    const float* w     = (const float*)d_in[1];  // [B, 1]
    const float* p     = (const float*)d_in[2];  // [1, 2]
    const float* W_in  = (const float*)d_in[3];  // [512, 130]
    const float* W_out = (const float*)d_in[4];  // [128, 512]
    float* out = (float*)d_out;

    const int B = in_sizes[0] / N_IN;

    init_kernel<<<1, 1>>>();
    fused_kernel<<<RB, RT>>>(x, w, p, W_in, W_out, out, B);
}

// round 11
// speedup vs baseline: 1.8876x; 1.0004x over previous
#include <cuda_runtime.h>
#include <cuda_bf16.h>

// Problem constants
#define N_IN   128
#define N_MID  512
#define N_CAT  130

#define RB     148               // blocks = SMs (co-residency for grid barrier)
#define RT     1024              // threads per block (32 warps)
#define WARPS  32
#define SLOTS  (RB * WARPS)      // 4736 warp-slots
#define PQ     33                // float4 quads per partial row (132 floats)

// Scratch (allocation-free)
__device__ float4       g_partial4[RB * PQ];
__device__ unsigned int g_bar;

// Tiny init: reset barrier counter each launch (keeps replays deterministic)
__global__ void init_kernel() { g_bar = 0u; }

// ---------------------------------------------------------------------------
// ONE persistent kernel:
//   phase 1: weighted reduction of x (forward, grid-strided per warp-slot)
//   grid barrier (all 148 blocks resident)
//   gemv (redundant per block, weights from L2): xpbar -> hbar -> o[128]
//   phase 2: out = x + o, each warp re-reads ITS OWN rows newest-first
//            (reverse k) so reads hit L2; __stcs writes stay evict-first.
// ---------------------------------------------------------------------------
__global__ __launch_bounds__(RT, 1)
void fused_kernel(const float* __restrict__ x,
                  const float* __restrict__ w,
                  const float* __restrict__ p,
                  const float* __restrict__ W_in,
                  const float* __restrict__ W_out,
                  float* __restrict__ out,
                  int B)
{
    const int t    = threadIdx.x;
    const int wid  = t >> 5;          // 0..31
    const int lane = t & 31;
    const int slot = blockIdx.x * WARPS + wid;

    const float4* __restrict__ x4 = reinterpret_cast<const float4*>(x);
    float4*       __restrict__ o4 = reinterpret_cast<float4*>(out);

    __shared__ float s_s[WARPS][N_IN];           // 16 KB
    __shared__ float s_w[WARPS];
    __shared__ __align__(16) float fin[4 * PQ];  // 132

    // ---------------- phase 1: weighted reduction ----------------
    {
        float4 acc = make_float4(0.f, 0.f, 0.f, 0.f);
        float  accw = 0.f;

        #pragma unroll 4
        for (int b = slot; b < B; b += SLOTS) {
            const float  wv = __ldg(&w[b]);                      // warp-uniform
            const float4 xv = __ldg(&x4[(size_t)b * 32 + lane]);
            acc.x = fmaf(wv, xv.x, acc.x);
            acc.y = fmaf(wv, xv.y, acc.y);
            acc.z = fmaf(wv, xv.z, acc.z);
            acc.w = fmaf(wv, xv.w, acc.w);
            if (lane == 0) accw += wv;
        }

        reinterpret_cast<float4*>(s_s[wid])[lane] = acc;
        if (lane == 0) s_w[wid] = accw;
        __syncthreads();

        if (t < N_IN) {
            float v = 0.f;
            #pragma unroll
            for (int g = 0; g < WARPS; g++) v += s_s[g][t];
            fin[t] = v;
        } else if (t == N_IN) {
            float v = 0.f;
            #pragma unroll
            for (int g = 0; g < WARPS; g++) v += s_w[g];
            fin[N_IN] = v;
        } else if (t < 4 * PQ) {
            fin[t] = 0.f;                                        // pad 129..131
        }
        __syncthreads();

        if (t < PQ)
            g_partial4[blockIdx.x * PQ + t] =
                reinterpret_cast<const float4*>(fin)[t];
    }

    // ---------------- grid barrier ----------------
    __threadfence();          // publish g_partial4 (gpu scope)
    __syncthreads();
    if (t == 0) {
        atomicAdd(&g_bar, 1u);
        while (*((volatile unsigned int*)&g_bar) < (unsigned int)RB) { }
        __threadfence();      // acquire: order subsequent partial reads
    }
    __syncthreads();

    // ---------------- gemv (redundant per block, all from L2) ----------------
    __shared__ float tmp[7][4 * PQ];             // 7 x 132
    __shared__ __align__(16) float xp[132];
    __shared__ __align__(16) float hb[N_MID];
    __shared__ __align__(16) float so[N_IN];

    // funnel 148 partial rows -> colsum
    if (t < 7 * 132) {                            // 924 threads
        const int col = t % 132, g = t / 132;
        const float* __restrict__ gp = reinterpret_cast<const float*>(g_partial4);
        float v = 0.f;
        #pragma unroll 4
        for (int r = g; r < RB; r += 7) v += gp[r * 132 + col];
        tmp[g][col] = v;
    }
    __syncthreads();
    if (t < 132) {
        float v = 0.f;
        #pragma unroll
        for (int g = 0; g < 7; g++) v += tmp[g][t];
        tmp[0][t] = v;                            // colsum
    }
    __syncthreads();
    if (t < N_IN) {
        xp[t] = tmp[0][t] / tmp[0][N_IN];
    } else if (t == N_IN) {
        xp[N_IN]     = __ldg(&p[0]);
        xp[N_IN + 1] = __ldg(&p[1]);
        xp[130] = 0.f; xp[131] = 0.f;
    }
    __syncthreads();

    // hbar = relu(W_in @ xpbar): warp-per-row, 16 rows/warp, float2 rows
    {
        const float2* __restrict__ xp2 = reinterpret_cast<const float2*>(xp);
        const float2 x0 = xp2[lane];
        const float2 x1 = xp2[lane + 32];
        #pragma unroll 2
        for (int r = wid; r < N_MID; r += WARPS) {
            const float2* __restrict__ row =
                reinterpret_cast<const float2*>(W_in + (size_t)r * N_CAT);
            const float2 w0 = __ldg(&row[lane]);
            const float2 w1 = __ldg(&row[lane + 32]);
            float a = fmaf(w0.x, x0.x, w0.y * x0.y);
            a = fmaf(w1.x, x1.x, fmaf(w1.y, x1.y, a));
            if (lane == 0) {                      // cols 128,129
                const float2 w2 = __ldg(&row[64]);
                a = fmaf(w2.x, xp[128], fmaf(w2.y, xp[129], a));
            }
            #pragma unroll
            for (int s = 16; s; s >>= 1) a += __shfl_xor_sync(0xFFFFFFFFu, a, s);
            if (lane == 0) hb[r] = fmaxf(a, 0.f);
        }
    }
    __syncthreads();

    // o = W_out @ hbar: warp-per-row, 4 rows/warp, float4 rows
    {
        const float4* __restrict__ hb4 = reinterpret_cast<const float4*>(hb);
        const float4 h0 = hb4[lane];
        const float4 h1 = hb4[lane + 32];
        const float4 h2 = hb4[lane + 64];
        const float4 h3 = hb4[lane + 96];
        #pragma unroll
        for (int r = wid; r < N_IN; r += WARPS) {
            const float4* __restrict__ row =
                reinterpret_cast<const float4*>(W_out + (size_t)r * N_MID);
            const float4 w0 = __ldg(&row[lane]);
            const float4 w1 = __ldg(&row[lane + 32]);
            const float4 w2 = __ldg(&row[lane + 64]);
            const float4 w3 = __ldg(&row[lane + 96]);
            float a = fmaf(w0.x, h0.x, w0.y * h0.y);
            a = fmaf(w0.z, h0.z, fmaf(w0.w, h0.w, a));
            a = fmaf(w1.x, h1.x, fmaf(w1.y, h1.y, a));
            a = fmaf(w1.z, h1.z, fmaf(w1.w, h1.w, a));
            a = fmaf(w2.x, h2.x, fmaf(w2.y, h2.y, a));
            a = fmaf(w2.z, h2.z, fmaf(w2.w, h2.w, a));
            a = fmaf(w3.x, h3.x, fmaf(w3.y, h3.y, a));
            a = fmaf(w3.z, h3.z, fmaf(w3.w, h3.w, a));
            #pragma unroll
            for (int s = 16; s; s >>= 1) a += __shfl_xor_sync(0xFFFFFFFFu, a, s);
            if (lane == 0) so[r] = a;
        }
    }
    __syncthreads();

    // ---------------- phase 2: out = x + o (reverse over own rows) ----------
    {
        const float4 ov = reinterpret_cast<const float4*>(so)[lane];
        if (slot < B) {
            const int kmax = (B - 1 - slot) / SLOTS + 1;  // rows for this slot
            #pragma unroll 4
            for (int k = kmax - 1; k >= 0; --k) {
                const size_t b = (size_t)slot + (size_t)k * SLOTS;
                float4 xv = __ldg(&x4[b * 32 + lane]);
                xv.x += ov.x; xv.y += ov.y; xv.z += ov.z; xv.w += ov.w;
                __stcs(&o4[b * 32 + lane], xv);           // evict-first store
            }
        }
    }
}

// ---------------------------------------------------------------------------
extern "C" void kernel_launch(void* const* d_in, const int* in_sizes, int n_in,
                              void* d_out, int out_size)
{
    const float* x     = (const float*)d_in[0];  // [B, 128]
    const float* w     = (const float*)d_in[1];  // [B, 1]
    const float* p     = (const float*)d_in[2];  // [1, 2]
    const float* W_in  = (const float*)d_in[3];  // [512, 130]
    const float* W_out = (const float*)d_in[4];  // [128, 512]
    float* out = (float*)d_out;

    const int B = in_sizes[0] / N_IN;

    init_kernel<<<1, 1>>>();
    fused_kernel<<<RB, RT>>>(x, w, p, W_in, W_out, out, B);
}

// round 12
// speedup vs baseline: 1.8916x; 1.0021x over previous
#include <cuda_runtime.h>
#include <cuda_bf16.h>

// Problem constants
#define N_IN   128
#define N_MID  512
#define N_CAT  130

#define RB     148               // blocks = SMs (co-residency for grid barrier)
#define RT     1024              // threads per block (32 warps)
#define WARPS  32
#define SLOTS  (RB * WARPS)      // 4736 warp-slots
#define PQ     33                // float4 quads per partial row (132 floats)

// Scratch (allocation-free)
__device__ float4       g_partial4[RB * PQ];
__device__ unsigned int g_bar;

// Tiny init: reset barrier counter each launch (keeps replays deterministic)
__global__ void init_kernel() { g_bar = 0u; }

// ---------------------------------------------------------------------------
// ONE persistent kernel:
//   phase 1: weighted reduction of x (forward, grid-strided per warp-slot)
//   grid barrier (all 148 blocks resident)
//   gemv (redundant per block, weights from L2): xpbar -> hbar -> o[128]
//   phase 2: out = x + o, each warp re-reads ITS OWN rows newest-first
//            (reverse k) so reads hit L2; __stcs writes stay evict-first.
// ---------------------------------------------------------------------------
__global__ __launch_bounds__(RT, 1)
void fused_kernel(const float* __restrict__ x,
                  const float* __restrict__ w,
                  const float* __restrict__ p,
                  const float* __restrict__ W_in,
                  const float* __restrict__ W_out,
                  float* __restrict__ out,
                  int B)
{
    const int t    = threadIdx.x;
    const int wid  = t >> 5;          // 0..31
    const int lane = t & 31;
    const int slot = blockIdx.x * WARPS + wid;

    const float4* __restrict__ x4 = reinterpret_cast<const float4*>(x);
    float4*       __restrict__ o4 = reinterpret_cast<float4*>(out);

    __shared__ float s_s[WARPS][N_IN];           // 16 KB
    __shared__ float s_w[WARPS];
    __shared__ __align__(16) float fin[4 * PQ];  // 132

    // ---------------- phase 1: weighted reduction ----------------
    {
        float4 acc = make_float4(0.f, 0.f, 0.f, 0.f);
        float  accw = 0.f;

        #pragma unroll 4
        for (int b = slot; b < B; b += SLOTS) {
            const float  wv = __ldg(&w[b]);                      // warp-uniform
            const float4 xv = __ldg(&x4[(size_t)b * 32 + lane]);
            acc.x = fmaf(wv, xv.x, acc.x);
            acc.y = fmaf(wv, xv.y, acc.y);
            acc.z = fmaf(wv, xv.z, acc.z);
            acc.w = fmaf(wv, xv.w, acc.w);
            if (lane == 0) accw += wv;
        }

        reinterpret_cast<float4*>(s_s[wid])[lane] = acc;
        if (lane == 0) s_w[wid] = accw;
        __syncthreads();

        if (t < N_IN) {
            float v = 0.f;
            #pragma unroll
            for (int g = 0; g < WARPS; g++) v += s_s[g][t];
            fin[t] = v;
        } else if (t == N_IN) {
            float v = 0.f;
            #pragma unroll
            for (int g = 0; g < WARPS; g++) v += s_w[g];
            fin[N_IN] = v;
        } else if (t < 4 * PQ) {
            fin[t] = 0.f;                                        // pad 129..131
        }
        __syncthreads();

        if (t < PQ)
            g_partial4[blockIdx.x * PQ + t] =
                reinterpret_cast<const float4*>(fin)[t];
    }

    // ---------------- grid barrier ----------------
    __threadfence();          // publish g_partial4 (gpu scope)
    __syncthreads();
    if (t == 0) {
        atomicAdd(&g_bar, 1u);
        while (*((volatile unsigned int*)&g_bar) < (unsigned int)RB) { }
        __threadfence();      // acquire: order subsequent partial reads
    }
    __syncthreads();

    // ---------------- gemv (redundant per block, all from L2) ----------------
    __shared__ float tmp[7][4 * PQ];             // 7 x 132
    __shared__ __align__(16) float xp[132];
    __shared__ __align__(16) float hb[N_MID];
    __shared__ __align__(16) float so[N_IN];

    // funnel 148 partial rows -> colsum
    if (t < 7 * 132) {                            // 924 threads
        const int col = t % 132, g = t / 132;
        const float* __restrict__ gp = reinterpret_cast<const float*>(g_partial4);
        float v = 0.f;
        #pragma unroll 4
        for (int r = g; r < RB; r += 7) v += gp[r * 132 + col];
        tmp[g][col] = v;
    }
    __syncthreads();
    if (t < 132) {
        float v = 0.f;
        #pragma unroll
        for (int g = 0; g < 7; g++) v += tmp[g][t];
        tmp[0][t] = v;                            // colsum
    }
    __syncthreads();
    if (t < N_IN) {
        xp[t] = tmp[0][t] / tmp[0][N_IN];
    } else if (t == N_IN) {
        xp[N_IN]     = __ldg(&p[0]);
        xp[N_IN + 1] = __ldg(&p[1]);
        xp[130] = 0.f; xp[131] = 0.f;
    }
    __syncthreads();

    // hbar = relu(W_in @ xpbar): warp-per-row, 16 rows/warp, float2 rows
    {
        const float2* __restrict__ xp2 = reinterpret_cast<const float2*>(xp);
        const float2 x0 = xp2[lane];
        const float2 x1 = xp2[lane + 32];
        #pragma unroll 2
        for (int r = wid; r < N_MID; r += WARPS) {
            const float2* __restrict__ row =
                reinterpret_cast<const float2*>(W_in + (size_t)r * N_CAT);
            const float2 w0 = __ldg(&row[lane]);
            const float2 w1 = __ldg(&row[lane + 32]);
            float a = fmaf(w0.x, x0.x, w0.y * x0.y);
            a = fmaf(w1.x, x1.x, fmaf(w1.y, x1.y, a));
            if (lane == 0) {                      // cols 128,129
                const float2 w2 = __ldg(&row[64]);
                a = fmaf(w2.x, xp[128], fmaf(w2.y, xp[129], a));
            }
            #pragma unroll
            for (int s = 16; s; s >>= 1) a += __shfl_xor_sync(0xFFFFFFFFu, a, s);
            if (lane == 0) hb[r] = fmaxf(a, 0.f);
        }
    }
    __syncthreads();

    // o = W_out @ hbar: warp-per-row, 4 rows/warp, float4 rows
    {
        const float4* __restrict__ hb4 = reinterpret_cast<const float4*>(hb);
        const float4 h0 = hb4[lane];
        const float4 h1 = hb4[lane + 32];
        const float4 h2 = hb4[lane + 64];
        const float4 h3 = hb4[lane + 96];
        #pragma unroll
        for (int r = wid; r < N_IN; r += WARPS) {
            const float4* __restrict__ row =
                reinterpret_cast<const float4*>(W_out + (size_t)r * N_MID);
            const float4 w0 = __ldg(&row[lane]);
            const float4 w1 = __ldg(&row[lane + 32]);
            const float4 w2 = __ldg(&row[lane + 64]);
            const float4 w3 = __ldg(&row[lane + 96]);
            float a = fmaf(w0.x, h0.x, w0.y * h0.y);
            a = fmaf(w0.z, h0.z, fmaf(w0.w, h0.w, a));
            a = fmaf(w1.x, h1.x, fmaf(w1.y, h1.y, a));
            a = fmaf(w1.z, h1.z, fmaf(w1.w, h1.w, a));
            a = fmaf(w2.x, h2.x, fmaf(w2.y, h2.y, a));
            a = fmaf(w2.z, h2.z, fmaf(w2.w, h2.w, a));
            a = fmaf(w3.x, h3.x, fmaf(w3.y, h3.y, a));
            a = fmaf(w3.z, h3.z, fmaf(w3.w, h3.w, a));
            #pragma unroll
            for (int s = 16; s; s >>= 1) a += __shfl_xor_sync(0xFFFFFFFFu, a, s);
            if (lane == 0) so[r] = a;
        }
    }
    __syncthreads();

    // ---------------- phase 2: out = x + o (reverse over own rows) ----------
    {
        const float4 ov = reinterpret_cast<const float4*>(so)[lane];
        if (slot < B) {
            const int kmax = (B - 1 - slot) / SLOTS + 1;  // rows for this slot
            #pragma unroll 4
            for (int k = kmax - 1; k >= 0; --k) {
                const size_t b = (size_t)slot + (size_t)k * SLOTS;
                float4 xv = __ldg(&x4[b * 32 + lane]);
                xv.x += ov.x; xv.y += ov.y; xv.z += ov.z; xv.w += ov.w;
                __stcs(&o4[b * 32 + lane], xv);           // evict-first store
            }
        }
    }
}

// ---------------------------------------------------------------------------
extern "C" void kernel_launch(void* const* d_in, const int* in_sizes, int n_in,
                              void* d_out, int out_size)
{
    const float* x     = (const float*)d_in[0];  // [B, 128]
    const float* w     = (const float*)d_in[1];  // [B, 1]
    const float* p     = (const float*)d_in[2];  // [1, 2]
    const float* W_in  = (const float*)d_in[3];  // [512, 130]
    const float* W_out = (const float*)d_in[4];  // [128, 512]
    float* out = (float*)d_out;

    const int B = in_sizes[0] / N_IN;

    init_kernel<<<1, 1>>>();
    fused_kernel<<<RB, RT>>>(x, w, p, W_in, W_out, out, B);
}